// round 12
// baseline (speedup 1.0000x reference)
#include <cuda_runtime.h>
#include <cuda_fp16.h>
#include <cstdint>

// Problem constants (fixed by reference setup_inputs)
#define C_CLS 256
#define S_SUP 5
#define Q_QRY 64
#define DIN   1024
#define ZD    128
#define CS    (C_CLS*S_SUP)              // 1280
#define CQ    (C_CLS*Q_QRY)              // 16384
#define M_TOT (CS+CQ)                    // 17664
#define NPAIRS (C_CLS*(Q_QRY*(Q_QRY-1)/2)) // 516096
#define EPSF  1e-8f
#define NSTG  64                          // k_gemm: K stages of 16
#define DLSTG 8                           // k_dloo: K stages of 16

// k_gemm smem (halves/buffer): Ah 2048 | Al 2048 | Bh 1024 | Bl 1024
#define G2_AL  2048
#define G2_BH  4096
#define G2_BL  5120
#define G2_BUF 6144                       // 12 KB / buffer
// k_dloo smem (halves/buffer): Ah 1024 | Al 1024 | Bh 4096 | Bl 4096
#define D2_AL  1024
#define D2_BH  2048
#define D2_BL  6144
#define D2_BUF 10240                      // 20 KB / buffer

// ---------------- device scratch (no allocations allowed) ----------------
__device__ __align__(16) float g_z[(size_t)M_TOT * ZD];        // ~9 MB
__device__ __align__(16) float g_proto2[C_CLS];                // ||proto_c||^2
__device__ __align__(16) float g_row2[M_TOT];                  // ||z_row||^2 (atomic-accumulated)
// 32*W fp16 hi/lo images: [k16(64)][n(128)][16 pos]
__device__ __align__(16) __half g_Wh[64 * 2048];               // 256 KB
__device__ __align__(16) __half g_Wl[64 * 2048];               // 256 KB
// protoT fp16 hi/lo images: [k16(8)][n(256)][16 pos]
__device__ __align__(16) __half g_Ph[8 * 4096];                // 64 KB
__device__ __align__(16) __half g_Pl[8 * 4096];                // 64 KB
__device__ float g_cos_sum;
__device__ float g_acc_cnt;

// ---------------- helpers ----------------
__device__ __forceinline__ uint32_t smem_u32(const void* p){
    uint32_t a; asm("{ .reg .u64 t; cvta.to.shared.u64 t, %1; cvt.u32.u64 %0, t; }"
                    : "=r"(a) : "l"(p));
    return a;
}
__device__ __forceinline__ void cp16(uint32_t saddr, const void* g){
    asm volatile("cp.async.cg.shared.global [%0], [%1], 16;" :: "r"(saddr), "l"(g));
}
#define CP_COMMIT() asm volatile("cp.async.commit_group;" ::: "memory")
#define CP_WAIT0()  asm volatile("cp.async.wait_group 0;"  ::: "memory")

// D += A(16x16,row) * B(16x8,col)  fp16 inputs, fp32 accumulate
__device__ __forceinline__ void mma16(float4 &d, uint32_t a0, uint32_t a1,
                                      uint32_t a2, uint32_t a3,
                                      uint32_t b0, uint32_t b1){
    asm volatile("mma.sync.aligned.m16n8k16.row.col.f32.f16.f16.f32 "
        "{%0,%1,%2,%3}, {%4,%5,%6,%7}, {%8,%9}, {%0,%1,%2,%3};"
        : "+f"(d.x), "+f"(d.y), "+f"(d.z), "+f"(d.w)
        : "r"(a0), "r"(a1), "r"(a2), "r"(a3), "r"(b0), "r"(b1));
}
// split float2 -> fp16 hi (packed) + exact residual lo (packed)
__device__ __forceinline__ void hsplit2(float2 v, uint32_t &hi, uint32_t &lo){
    __half2 h = __float22half2_rn(v);
    float2 hf = __half22float2(h);
    __half2 l = __float22half2_rn(make_float2(v.x - hf.x, v.y - hf.y));
    hi = *(uint32_t*)&h;
    lo = *(uint32_t*)&l;
}

// =====================================================================
// KW: split 32*W into fp16 hi/lo images [k16 s][n][16 pos],
// pos block t = k {2t,2t+1,2t+8,2t+9}. Also zeroes g_row2 + accumulators.
// =====================================================================
__global__ __launch_bounds__(256) void k_wsplit(const float* __restrict__ W){
    const int s = blockIdx.x;            // 0..63
    const int n = threadIdx.x >> 1;
    const int h = threadIdx.x & 1;
    // zero g_row2 (64 blocks x 256 threads = 16384 lanes)
    for (int i = blockIdx.x * 256 + threadIdx.x; i < M_TOT; i += 64 * 256)
        g_row2[i] = 0.0f;
    if (s == 0 && threadIdx.x == 0){ g_cos_sum = 0.0f; g_acc_cnt = 0.0f; }
#pragma unroll
    for (int dt = 0; dt < 2; dt++){
        const int t  = 2 * h + dt;
        const int kb = s * 16 + 2 * t;
        const float2 vab = make_float2(32.f * W[(size_t)(kb + 0) * ZD + n],
                                       32.f * W[(size_t)(kb + 1) * ZD + n]);
        const float2 vcd = make_float2(32.f * W[(size_t)(kb + 8) * ZD + n],
                                       32.f * W[(size_t)(kb + 9) * ZD + n]);
        uint32_t h01, l01, h89, l89;
        hsplit2(vab, h01, l01);
        hsplit2(vcd, h89, l89);
        const int off = s * 2048 + n * 16 + t * 4;
        *(uint2*)&g_Wh[off] = make_uint2(h01, h89);
        *(uint2*)&g_Wl[off] = make_uint2(l01, l89);
    }
}

// =====================================================================
// K1: z = [xs; xq] @ W, fp16 double-double (3-pass m16n8k16).
// Grid (138, 2): block tile 128 x 64, 256 threads = 8 warps (4m x 2n),
// warp tile 32x32. 2 CTAs/SM (12KB x2 smem, <=128 regs) -> 32 warps/SM.
// Row norms: CTA-partial, atomicAdd into zeroed g_row2 (2 adds/row,
// commutative -> deterministic). Epilogue z = acc/32.
// =====================================================================
__global__ __launch_bounds__(256, 2) void k_gemm(const float* __restrict__ xs,
                                                 const float* __restrict__ xq){
    extern __shared__ __half sh[];       // 2 x G2_BUF halves (24 KB)
    __shared__ float s_r2[128];

    const int tid  = threadIdx.x;
    const int lane = tid & 31;
    const int wid  = tid >> 5;           // 0..7
    const int g    = lane >> 2;
    const int tg   = lane & 3;
    const int m0   = (wid & 3) * 32;
    const int n0   = (wid >> 2) * 32;    // local n within 64-col block
    const int bm   = blockIdx.x;
    const int bn   = blockIdx.y;         // 0/1 (64-col halves)
    const float* X = (bm < 10) ? (xs + (size_t)bm * (128 * DIN))
                               : (xq + (size_t)(bm - 10) * (128 * DIN));
    const int sm_m = tid >> 1;           // staging row 0..127
    const int shf  = tid & 1;            // staging half
    const int sts_off = sm_m * 16 + shf * 8;
    const __half* WH = g_Wh + bn * 1024;
    const __half* WL = g_Wl + bn * 1024;

    float4 acc[2][4];
#pragma unroll
    for (int i = 0; i < 2; i++)
#pragma unroll
        for (int j = 0; j < 4; j++) acc[i][j] = make_float4(0.f, 0.f, 0.f, 0.f);

    float4 rA0, rA1;
    // prologue: stage 0
    {
        __half* buf = sh;
        if (tid < 128) cp16(smem_u32(&buf[G2_BH]) + tid * 16, WH + tid * 8);
        else           cp16(smem_u32(&buf[G2_BL]) + (tid - 128) * 16, WL + (tid - 128) * 8);
        CP_COMMIT();
        const float* xp = X + (size_t)sm_m * DIN + 4 * shf;
        rA0 = *(const float4*)xp;        // k 4h..4h+3
        rA1 = *(const float4*)(xp + 8);  // k 8+4h..11+4h
        uint32_t hA, lA, hB, lB, hC, lC, hD, lD;
        hsplit2(make_float2(rA0.x, rA0.y), hA, lA);
        hsplit2(make_float2(rA1.x, rA1.y), hB, lB);
        hsplit2(make_float2(rA0.z, rA0.w), hC, lC);
        hsplit2(make_float2(rA1.z, rA1.w), hD, lD);
        *(uint4*)&buf[sts_off]         = make_uint4(hA, hB, hC, hD);
        *(uint4*)&buf[G2_AL + sts_off] = make_uint4(lA, lB, lC, lD);
        CP_WAIT0();
    }
    __syncthreads();

    for (int s = 0; s < NSTG; s++){
        const int b = s & 1;
        const __half* buf = sh + b * G2_BUF;
        __half* nbuf = sh + (b ^ 1) * G2_BUF;
        if (s + 1 < NSTG){
            if (tid < 128) cp16(smem_u32(&nbuf[G2_BH]) + tid * 16,
                                WH + (s + 1) * 2048 + tid * 8);
            else           cp16(smem_u32(&nbuf[G2_BL]) + (tid - 128) * 16,
                                WL + (s + 1) * 2048 + (tid - 128) * 8);
            CP_COMMIT();
            const float* xp = X + (size_t)sm_m * DIN + (s + 1) * 16 + 4 * shf;
            rA0 = *(const float4*)xp;
            rA1 = *(const float4*)(xp + 8);
        }
        uint2 AH[2][2], AL[2][2];
#pragma unroll
        for (int mt = 0; mt < 2; mt++){
            const int r0 = (m0 + mt * 16 + g) * 16 + tg * 4;
            AH[mt][0] = *(const uint2*)&buf[r0];
            AH[mt][1] = *(const uint2*)&buf[r0 + 128];          // row +8
            AL[mt][0] = *(const uint2*)&buf[G2_AL + r0];
            AL[mt][1] = *(const uint2*)&buf[G2_AL + r0 + 128];
        }
#pragma unroll
        for (int j = 0; j < 4; j++){
            const int nb = (n0 + j * 8 + g) * 16 + tg * 4;
            const uint2 bh = *(const uint2*)&buf[G2_BH + nb];
            const uint2 bl = *(const uint2*)&buf[G2_BL + nb];
#pragma unroll
            for (int mt = 0; mt < 2; mt++){
                mma16(acc[mt][j], AH[mt][0].x, AH[mt][1].x, AH[mt][0].y, AH[mt][1].y, bh.x, bh.y);
                mma16(acc[mt][j], AL[mt][0].x, AL[mt][1].x, AL[mt][0].y, AL[mt][1].y, bh.x, bh.y);
                mma16(acc[mt][j], AH[mt][0].x, AH[mt][1].x, AH[mt][0].y, AH[mt][1].y, bl.x, bl.y);
            }
        }
        if (s + 1 < NSTG){
            uint32_t hA, lA, hB, lB, hC, lC, hD, lD;
            hsplit2(make_float2(rA0.x, rA0.y), hA, lA);
            hsplit2(make_float2(rA1.x, rA1.y), hB, lB);
            hsplit2(make_float2(rA0.z, rA0.w), hC, lC);
            hsplit2(make_float2(rA1.z, rA1.w), hD, lD);
            *(uint4*)&nbuf[sts_off]         = make_uint4(hA, hB, hC, hD);
            *(uint4*)&nbuf[G2_AL + sts_off] = make_uint4(lA, lB, lC, lD);
            CP_WAIT0();
            __syncthreads();
        }
    }

    // ---- epilogue: z = acc/32, store + CTA-partial row norms ----
    if (tid < 128) s_r2[tid] = 0.0f;
    __syncthreads();
    const size_t rb = (size_t)bm * 128;
    const int cb = bn * 64;
    const float inv32 = 1.0f / 32.0f;
#pragma unroll
    for (int mt = 0; mt < 2; mt++){
        const int r0 = m0 + mt * 16 + g;
        float s0 = 0.0f, s1 = 0.0f;
#pragma unroll
        for (int j = 0; j < 4; j++){
            float4 a = acc[mt][j];
            a.x *= inv32; a.y *= inv32; a.z *= inv32; a.w *= inv32;
            const int col = cb + n0 + j * 8 + 2 * tg;
            *(float2*)(g_z + (rb + r0) * ZD + col)     = make_float2(a.x, a.y);
            *(float2*)(g_z + (rb + r0 + 8) * ZD + col) = make_float2(a.z, a.w);
            s0 = fmaf(a.x, a.x, s0); s0 = fmaf(a.y, a.y, s0);
            s1 = fmaf(a.z, a.z, s1); s1 = fmaf(a.w, a.w, s1);
        }
        s0 += __shfl_xor_sync(0xffffffffu, s0, 1);
        s0 += __shfl_xor_sync(0xffffffffu, s0, 2);
        s1 += __shfl_xor_sync(0xffffffffu, s1, 1);
        s1 += __shfl_xor_sync(0xffffffffu, s1, 2);
        if (tg == 0){
            atomicAdd(&s_r2[r0],     s0);
            atomicAdd(&s_r2[r0 + 8], s1);
        }
    }
    __syncthreads();
    if (tid < 128) atomicAdd(&g_row2[rb + tid], s_r2[tid]);
}

// ---------------- K2: prototypes + ||proto||^2 + fp16 hi/lo images ------
__global__ __launch_bounds__(128) void k_proto(){
    const int c = blockIdx.x;
    const int d = threadIdx.x;  // 0..127 (= k index)
    const float* z = g_z + (size_t)c * S_SUP * ZD + d;
    float p = 0.0f;
#pragma unroll
    for (int s = 0; s < S_SUP; s++) p += z[s * ZD];
    p *= (1.0f / S_SUP);
    const int k16 = d >> 4;
    const int kk  = d & 15;
    const int pos = ((kk >> 1) & 3) * 4 + ((kk >> 3) & 1) * 2 + (kk & 1);
    const __half hi = __float2half_rn(p);
    const int off = k16 * 4096 + c * 16 + pos;
    g_Ph[off] = hi;
    g_Pl[off] = __float2half_rn(p - __half2float(hi));
    float sq = p * p;
#pragma unroll
    for (int o = 16; o; o >>= 1) sq += __shfl_xor_sync(0xffffffffu, sq, o);
    __shared__ float w[4];
    if ((d & 31) == 0) w[d >> 5] = sq;
    __syncthreads();
    if (d == 0) g_proto2[c] = w[0] + w[1] + w[2] + w[3];
}

// =====================================================================
// K3 (fused d2 + loo): one CTA per class. GEMM M=64 x N=256 x K=128,
// fp16 double-double 3-pass. 256 threads = 8 warps (2m x 4n), warp
// tile 32x64 (acc[2][8]). 2 CTAs/SM (67.6KB smem, <=128 regs); grid
// 256 = one wave. d2 -> SMEM (stride 264) then loo-norm + cos + argmin.
// cos: sum_{q<k} a_q.a_k = ( ||sum_q a_q||^2 - sum_q ||a_q||^2 ) / 2
// =====================================================================
__global__ __launch_bounds__(256, 2) void k_dloo(){
    extern __shared__ __half sh[];       // buffers; d2s aliases as float*
    __shared__ float s_part[8][256];
    __shared__ float s_red[8];
    __shared__ float s_scal[2];          // [sumA2, cnt]

    const int tid  = threadIdx.x;
    const int lane = tid & 31;
    const int wid  = tid >> 5;           // 0..7
    const int g    = lane >> 2;
    const int tg   = lane & 3;
    const int m0   = (wid & 1) * 32;
    const int n0   = (wid >> 1) * 64;
    const int cls  = blockIdx.x;         // one class per CTA
    const float* X = g_z + (size_t)(CS + cls * 64) * ZD;
    const int sm_m = tid >> 2;           // 0..63
    const int st   = tid & 3;
    const int sts_off = sm_m * 16 + st * 4;

    if (tid < 2) s_scal[tid] = 0.0f;

    float4 acc[2][8];
#pragma unroll
    for (int i = 0; i < 2; i++)
#pragma unroll
        for (int j = 0; j < 8; j++) acc[i][j] = make_float4(0.f, 0.f, 0.f, 0.f);

    float2 rA0, rA1;
    // prologue: stage 0
    {
        __half* buf = sh;
        const uint32_t bh = smem_u32(&buf[D2_BH]);
        const uint32_t bl = smem_u32(&buf[D2_BL]);
        cp16(bh + tid * 16,        g_Ph + tid * 8);
        cp16(bh + tid * 16 + 4096, g_Ph + tid * 8 + 2048);
        cp16(bl + tid * 16,        g_Pl + tid * 8);
        cp16(bl + tid * 16 + 4096, g_Pl + tid * 8 + 2048);
        CP_COMMIT();
        const float* xp = X + (size_t)sm_m * ZD + 2 * st;
        rA0 = *(const float2*)xp;
        rA1 = *(const float2*)(xp + 8);
        uint32_t h01, l01, h89, l89;
        hsplit2(rA0, h01, l01);
        hsplit2(rA1, h89, l89);
        *(uint2*)&buf[sts_off]         = make_uint2(h01, h89);
        *(uint2*)&buf[D2_AL + sts_off] = make_uint2(l01, l89);
        CP_WAIT0();
    }
    __syncthreads();

    for (int s = 0; s < DLSTG; s++){
        const int b = s & 1;
        const __half* buf = sh + b * D2_BUF;
        __half* nbuf = sh + (b ^ 1) * D2_BUF;
        if (s + 1 < DLSTG){
            const uint32_t bh = smem_u32(&nbuf[D2_BH]);
            const uint32_t bl = smem_u32(&nbuf[D2_BL]);
            const __half* sH = g_Ph + (s + 1) * 4096;
            const __half* sL = g_Pl + (s + 1) * 4096;
            cp16(bh + tid * 16,        sH + tid * 8);
            cp16(bh + tid * 16 + 4096, sH + tid * 8 + 2048);
            cp16(bl + tid * 16,        sL + tid * 8);
            cp16(bl + tid * 16 + 4096, sL + tid * 8 + 2048);
            CP_COMMIT();
            const float* xp = X + (size_t)sm_m * ZD + (s + 1) * 16 + 2 * st;
            rA0 = *(const float2*)xp;
            rA1 = *(const float2*)(xp + 8);
        }
        uint2 AH[2][2], AL[2][2];
#pragma unroll
        for (int mt = 0; mt < 2; mt++){
            const int r0 = (m0 + mt * 16 + g) * 16 + tg * 4;
            AH[mt][0] = *(const uint2*)&buf[r0];
            AH[mt][1] = *(const uint2*)&buf[r0 + 128];
            AL[mt][0] = *(const uint2*)&buf[D2_AL + r0];
            AL[mt][1] = *(const uint2*)&buf[D2_AL + r0 + 128];
        }
#pragma unroll
        for (int j = 0; j < 8; j++){
            const int nb = (n0 + j * 8 + g) * 16 + tg * 4;
            const uint2 bh = *(const uint2*)&buf[D2_BH + nb];
            const uint2 bl = *(const uint2*)&buf[D2_BL + nb];
#pragma unroll
            for (int mt = 0; mt < 2; mt++){
                mma16(acc[mt][j], AH[mt][0].x, AH[mt][1].x, AH[mt][0].y, AH[mt][1].y, bh.x, bh.y);
                mma16(acc[mt][j], AL[mt][0].x, AL[mt][1].x, AL[mt][0].y, AL[mt][1].y, bh.x, bh.y);
                mma16(acc[mt][j], AH[mt][0].x, AH[mt][1].x, AH[mt][0].y, AH[mt][1].y, bl.x, bl.y);
            }
        }
        if (s + 1 < DLSTG){
            uint32_t h01, l01, h89, l89;
            hsplit2(rA0, h01, l01);
            hsplit2(rA1, h89, l89);
            *(uint2*)&nbuf[sts_off]         = make_uint2(h01, h89);
            *(uint2*)&nbuf[D2_AL + sts_off] = make_uint2(l01, l89);
            CP_WAIT0();
            __syncthreads();
        }
    }

    // ---- d2 into SMEM (reuses stage buffers; stride 264 floats) ----
    __syncthreads();                     // all warps done reading buffers
    float* d2s = (float*)sh;             // 64 x 264 floats
#pragma unroll
    for (int mt = 0; mt < 2; mt++){
        const int r = m0 + mt * 16 + g;
        const float qn0 = g_row2[CS + cls * 64 + r];
        const float qn1 = g_row2[CS + cls * 64 + r + 8];
#pragma unroll
        for (int j = 0; j < 8; j++){
            const int col = n0 + j * 8 + 2 * tg;
            const float pn0 = g_proto2[col];
            const float pn1 = g_proto2[col + 1];
            const float4 a = acc[mt][j];
            *(float2*)&d2s[r * 264 + col] =
                make_float2(qn0 + pn0 - 2.0f * a.x, qn0 + pn1 - 2.0f * a.y);
            *(float2*)&d2s[(r + 8) * 264 + col] =
                make_float2(qn1 + pn0 - 2.0f * a.z, qn1 + pn1 - 2.0f * a.w);
        }
    }
    __syncthreads();

    // ---- loo: warp w -> rows w*8..w*8+7; lane owns 8 cols ----
    const float* D = d2s + (size_t)(wid * 8) * 264 + lane * 8;
    float d2v[8][8];
#pragma unroll
    for (int r = 0; r < 8; r++){
        const float4 v0 = *(const float4*)(D + r * 264);
        const float4 v1 = *(const float4*)(D + r * 264 + 4);
        d2v[r][0] = v0.x; d2v[r][1] = v0.y; d2v[r][2] = v0.z; d2v[r][3] = v0.w;
        d2v[r][4] = v1.x; d2v[r][5] = v1.y; d2v[r][6] = v1.z; d2v[r][7] = v1.w;
    }

    float sacc[8];
#pragma unroll
    for (int j = 0; j < 8; j++) sacc[j] = 0.0f;
    float sumA2 = 0.0f;
    float cnt   = 0.0f;

#pragma unroll
    for (int r = 0; r < 8; r++){
        float ss = 0.0f;
        float mv = 3.4e38f;
        int   mi = 1 << 30;
#pragma unroll
        for (int j = 0; j < 8; j++){
            const int   p = lane * 8 + j;
            const float v = d2v[r][j];
            if (v < mv){ mv = v; mi = p; }        // ascending -> first min
            if (p != cls) ss = fmaf(v, v, ss);
        }
#pragma unroll
        for (int off = 16; off; off >>= 1){
            ss += __shfl_xor_sync(0xffffffffu, ss, off);
            const float ov = __shfl_xor_sync(0xffffffffu, mv, off);
            const int   oi = __shfl_xor_sync(0xffffffffu, mi, off);
            if (ov < mv || (ov == mv && oi < mi)){ mv = ov; mi = oi; }
        }
        const float inv = 1.0f / fmaxf(sqrtf(ss), EPSF);
#pragma unroll
        for (int j = 0; j < 8; j++){
            const int p = lane * 8 + j;
            if (p != cls) sacc[j] = fmaf(d2v[r][j], inv, sacc[j]);
        }
        if (lane == 0){
            sumA2 += ss * inv * inv;
            if (mi == cls) cnt += 1.0f;
        }
    }

#pragma unroll
    for (int j = 0; j < 8; j++) s_part[wid][lane * 8 + j] = sacc[j];
    if (lane == 0){
        atomicAdd(&s_scal[0], sumA2);
        atomicAdd(&s_scal[1], cnt);
    }
    __syncthreads();

    // ||sum_q a_q||^2
    float col = 0.0f;
#pragma unroll
    for (int w2 = 0; w2 < 8; w2++) col += s_part[w2][tid];
    float sq = col * col;
#pragma unroll
    for (int off = 16; off; off >>= 1) sq += __shfl_xor_sync(0xffffffffu, sq, off);
    if (lane == 0) s_red[wid] = sq;
    __syncthreads();
    if (tid == 0){
        float S2 = 0.0f;
#pragma unroll
        for (int i = 0; i < 8; i++) S2 += s_red[i];
        atomicAdd(&g_cos_sum, 0.5f * (S2 - s_scal[0]));
        atomicAdd(&g_acc_cnt, s_scal[1]);
    }
}

// ---------------- K4: finalize -------------------------------------------
__global__ void k_final(float* __restrict__ out){
    if (threadIdx.x == 0){
        out[0] = g_cos_sum / (float)NPAIRS;
        out[1] = g_acc_cnt / (float)CQ;
    }
}

// ---------------- launch ---------------------------------------------------
extern "C" void kernel_launch(void* const* d_in, const int* in_sizes, int n_in,
                              void* d_out, int out_size){
    const float* xs = (const float*)d_in[0];
    const float* xq = (const float*)d_in[1];
    const float* W  = (const float*)d_in[2];
    float* out = (float*)d_out;
    (void)in_sizes; (void)n_in; (void)out_size;

    const int smem_gemm = 2 * G2_BUF * (int)sizeof(__half);    // 24 KB
    const int smem_dloo = 64 * 264 * (int)sizeof(float);       // 67.6 KB (>= 2*D2_BUF*2B)
    cudaFuncSetAttribute(k_gemm, cudaFuncAttributeMaxDynamicSharedMemorySize, smem_gemm);
    cudaFuncSetAttribute(k_dloo, cudaFuncAttributeMaxDynamicSharedMemorySize, smem_dloo);

    k_wsplit<<<64, 256>>>(W);
    k_gemm<<<dim3(M_TOT / 128, 2), 256, smem_gemm>>>(xs, xq);
    k_proto<<<C_CLS, 128>>>();
    k_dloo<<<C_CLS, 256, smem_dloo>>>();
    k_final<<<1, 1>>>(out);
}

// round 13
// speedup vs baseline: 1.1242x; 1.1242x over previous
#include <cuda_runtime.h>
#include <cuda_fp16.h>
#include <cstdint>

// Problem constants (fixed by reference setup_inputs)
#define C_CLS 256
#define S_SUP 5
#define Q_QRY 64
#define DIN   1024
#define ZD    128
#define CS    (C_CLS*S_SUP)              // 1280
#define CQ    (C_CLS*Q_QRY)              // 16384
#define M_TOT (CS+CQ)                    // 17664
#define NPAIRS (C_CLS*(Q_QRY*(Q_QRY-1)/2)) // 516096
#define EPSF  1e-8f
#define NSTG  64                          // k_gemm: K stages of 16
#define DLSTG 8                           // k_dloo: K stages of 16

// k_gemm smem (halves/buffer): Ah 2048 | Al 2048 | Bh 2048 | Bl 2048
#define G_AL  2048
#define G_BH  4096
#define G_BL  6144
#define G_BUF 8192                        // 16 KB / buffer
// k_dloo smem (halves/buffer): Ah|Al (2048 each) | Bh|Bl (4096 each)
#define D_AL  2048
#define D_BH  4096
#define D_BL  8192
#define D_BUF 12288                       // 24 KB / buffer

// ---------------- device scratch (no allocations allowed) ----------------
__device__ __align__(16) float g_z[(size_t)M_TOT * ZD];        // ~9 MB
__device__ __align__(16) float g_proto2[C_CLS];                // ||proto_c||^2
__device__ __align__(16) float g_row2[M_TOT];                  // ||z_row||^2
// 32*W fp16 hi/lo images: [k16(64)][n(128)][16 pos]
__device__ __align__(16) __half g_Wh[64 * 2048];               // 256 KB
__device__ __align__(16) __half g_Wl[64 * 2048];               // 256 KB
// protoT fp16 hi/lo images: [k16(8)][n(256)][16 pos]
__device__ __align__(16) __half g_Ph[8 * 4096];                // 64 KB
__device__ __align__(16) __half g_Pl[8 * 4096];                // 64 KB
__device__ float g_cos_sum;
__device__ float g_acc_cnt;

// ---------------- helpers ----------------
__device__ __forceinline__ uint32_t smem_u32(const void* p){
    uint32_t a; asm("{ .reg .u64 t; cvta.to.shared.u64 t, %1; cvt.u32.u64 %0, t; }"
                    : "=r"(a) : "l"(p));
    return a;
}
__device__ __forceinline__ void cp16(uint32_t saddr, const void* g){
    asm volatile("cp.async.cg.shared.global [%0], [%1], 16;" :: "r"(saddr), "l"(g));
}
#define CP_COMMIT() asm volatile("cp.async.commit_group;" ::: "memory")
#define CP_WAIT0()  asm volatile("cp.async.wait_group 0;"  ::: "memory")

// D += A(16x16,row) * B(16x8,col)  fp16 inputs, fp32 accumulate
__device__ __forceinline__ void mma16(float4 &d, uint32_t a0, uint32_t a1,
                                      uint32_t a2, uint32_t a3,
                                      uint32_t b0, uint32_t b1){
    asm volatile("mma.sync.aligned.m16n8k16.row.col.f32.f16.f16.f32 "
        "{%0,%1,%2,%3}, {%4,%5,%6,%7}, {%8,%9}, {%0,%1,%2,%3};"
        : "+f"(d.x), "+f"(d.y), "+f"(d.z), "+f"(d.w)
        : "r"(a0), "r"(a1), "r"(a2), "r"(a3), "r"(b0), "r"(b1));
}
// split float2 -> fp16 hi (packed) + exact residual lo (packed)
__device__ __forceinline__ void hsplit2(float2 v, uint32_t &hi, uint32_t &lo){
    __half2 h = __float22half2_rn(v);
    float2 hf = __half22float2(h);
    __half2 l = __float22half2_rn(make_float2(v.x - hf.x, v.y - hf.y));
    hi = *(uint32_t*)&h;
    lo = *(uint32_t*)&l;
}

// =====================================================================
// KW: split 32*W[k=1024][n=128] into fp16 hi/lo images.
// Layout [k16 s][n][pos], pos block t (4 halves) = k {2t,2t+1,2t+8,2t+9}.
// =====================================================================
__global__ __launch_bounds__(256) void k_wsplit(const float* __restrict__ W){
    const int s = blockIdx.x;            // 0..63
    const int n = threadIdx.x >> 1;
    const int h = threadIdx.x & 1;
#pragma unroll
    for (int dt = 0; dt < 2; dt++){
        const int t  = 2 * h + dt;
        const int kb = s * 16 + 2 * t;
        const float2 vab = make_float2(32.f * W[(size_t)(kb + 0) * ZD + n],
                                       32.f * W[(size_t)(kb + 1) * ZD + n]);
        const float2 vcd = make_float2(32.f * W[(size_t)(kb + 8) * ZD + n],
                                       32.f * W[(size_t)(kb + 9) * ZD + n]);
        uint32_t h01, l01, h89, l89;
        hsplit2(vab, h01, l01);
        hsplit2(vcd, h89, l89);
        const int off = s * 2048 + n * 16 + t * 4;
        *(uint2*)&g_Wh[off] = make_uint2(h01, h89);
        *(uint2*)&g_Wl[off] = make_uint2(l01, l89);
    }
}

// =====================================================================
// K1: z = [xs; xq] @ W, fp16 double-double (3-pass m16n8k16).
// 1024 threads = 32 warps (8m x 4n), warp tile 16x32 -> 8 warps/SMSP.
// Block tile 128x128, K=16/stage, 64 stages double-buffered (32 KB).
// B via cp.async from prebuilt hi/lo images; A split at staging
// (1 float2 per thread per stage). Epilogue: z = acc/32 + ||row||^2.
// =====================================================================
__global__ __launch_bounds__(1024, 1) void k_gemm(const float* __restrict__ xs,
                                                  const float* __restrict__ xq){
    extern __shared__ __half sh[];       // 2 x G_BUF halves (32 KB)
    __shared__ float s_r2[128];

    const int tid  = threadIdx.x;
    const int lane = tid & 31;
    const int wid  = tid >> 5;           // 0..31
    const int g    = lane >> 2;
    const int tg   = lane & 3;
    const int m0   = (wid & 7) * 16;
    const int n0   = (wid >> 3) * 32;
    const int bm   = blockIdx.x;
    const float* X = (bm < 10) ? (xs + (size_t)bm * (128 * DIN))
                               : (xq + (size_t)(bm - 10) * (128 * DIN));
    // staging: 1024 threads x 2 halves = 128 rows x 16 k
    const int sm_m = tid >> 3;           // row 0..127
    const int tb   = (tid >> 1) & 3;     // pos block 0..3
    const int hh   = tid & 1;            // k-half within block
    const int sts_off = sm_m * 16 + tb * 4 + hh * 2;   // halves (coalesced STS.32)
    const int k_off   = 2 * tb + 8 * hh;               // LDG k base

    float4 acc[4];
#pragma unroll
    for (int j = 0; j < 4; j++) acc[j] = make_float4(0.f, 0.f, 0.f, 0.f);

    float2 rA;
    // prologue: stage 0
    {
        __half* buf = sh;
        if (tid < 256)       cp16(smem_u32(&buf[G_BH]) + tid * 16, g_Wh + tid * 8);
        else if (tid < 512)  cp16(smem_u32(&buf[G_BL]) + (tid - 256) * 16,
                                  g_Wl + (tid - 256) * 8);
        CP_COMMIT();
        rA = *(const float2*)(X + (size_t)sm_m * DIN + k_off);
        uint32_t hi, lo;
        hsplit2(rA, hi, lo);
        *(uint32_t*)&buf[sts_off]        = hi;
        *(uint32_t*)&buf[G_AL + sts_off] = lo;
        CP_WAIT0();
    }
    __syncthreads();

    for (int s = 0; s < NSTG; s++){
        const int b = s & 1;
        const __half* buf = sh + b * G_BUF;
        __half* nbuf = sh + (b ^ 1) * G_BUF;
        if (s + 1 < NSTG){
            if (tid < 256)      cp16(smem_u32(&nbuf[G_BH]) + tid * 16,
                                     g_Wh + (s + 1) * 2048 + tid * 8);
            else if (tid < 512) cp16(smem_u32(&nbuf[G_BL]) + (tid - 256) * 16,
                                     g_Wl + (s + 1) * 2048 + (tid - 256) * 8);
            CP_COMMIT();
            rA = *(const float2*)(X + (size_t)sm_m * DIN + (s + 1) * 16 + k_off);
        }
        // A fragments (warp tile 16x32: one m-tile)
        const int r0 = (m0 + g) * 16 + tg * 4;
        const uint2 AH0 = *(const uint2*)&buf[r0];
        const uint2 AH1 = *(const uint2*)&buf[r0 + 128];       // row +8
        const uint2 AL0 = *(const uint2*)&buf[G_AL + r0];
        const uint2 AL1 = *(const uint2*)&buf[G_AL + r0 + 128];
#pragma unroll
        for (int j = 0; j < 4; j++){
            const int nb = (n0 + j * 8 + g) * 16 + tg * 4;
            const uint2 bh = *(const uint2*)&buf[G_BH + nb];
            const uint2 bl = *(const uint2*)&buf[G_BL + nb];
            mma16(acc[j], AH0.x, AH1.x, AH0.y, AH1.y, bh.x, bh.y);
            mma16(acc[j], AL0.x, AL1.x, AL0.y, AL1.y, bh.x, bh.y);
            mma16(acc[j], AH0.x, AH1.x, AH0.y, AH1.y, bl.x, bl.y);
        }
        if (s + 1 < NSTG){
            uint32_t hi, lo;
            hsplit2(rA, hi, lo);
            *(uint32_t*)&nbuf[sts_off]        = hi;
            *(uint32_t*)&nbuf[G_AL + sts_off] = lo;
            CP_WAIT0();
            __syncthreads();
        }
    }

    // ---- epilogue: z = acc/32, store + fused row norms ----
    if (tid < 128) s_r2[tid] = 0.0f;
    __syncthreads();
    const size_t rb = (size_t)bm * 128;
    const float inv32 = 1.0f / 32.0f;
    {
        const int r0 = m0 + g;
        float s0 = 0.0f, s1 = 0.0f;
#pragma unroll
        for (int j = 0; j < 4; j++){
            float4 a = acc[j];
            a.x *= inv32; a.y *= inv32; a.z *= inv32; a.w *= inv32;
            const int col = n0 + j * 8 + 2 * tg;
            *(float2*)(g_z + (rb + r0) * ZD + col)     = make_float2(a.x, a.y);
            *(float2*)(g_z + (rb + r0 + 8) * ZD + col) = make_float2(a.z, a.w);
            s0 = fmaf(a.x, a.x, s0); s0 = fmaf(a.y, a.y, s0);
            s1 = fmaf(a.z, a.z, s1); s1 = fmaf(a.w, a.w, s1);
        }
        s0 += __shfl_xor_sync(0xffffffffu, s0, 1);
        s0 += __shfl_xor_sync(0xffffffffu, s0, 2);
        s1 += __shfl_xor_sync(0xffffffffu, s1, 1);
        s1 += __shfl_xor_sync(0xffffffffu, s1, 2);
        if (tg == 0){
            atomicAdd(&s_r2[r0],     s0);
            atomicAdd(&s_r2[r0 + 8], s1);
        }
    }
    __syncthreads();
    if (tid < 128) g_row2[rb + tid] = s_r2[tid];
}

// ---------------- K2: prototypes + ||proto||^2 + fp16 hi/lo images ------
// Image [k16(8)][n(256)][16 pos]; pos for kk=d&15:
// pos = ((kk>>1)&3)*4 + ((kk>>3)&1)*2 + (kk&1). Zeroes accumulators.
__global__ __launch_bounds__(128) void k_proto(){
    const int c = blockIdx.x;
    const int d = threadIdx.x;  // 0..127 (= k index)
    if (c == 0 && d == 0){ g_cos_sum = 0.0f; g_acc_cnt = 0.0f; }
    const float* z = g_z + (size_t)c * S_SUP * ZD + d;
    float p = 0.0f;
#pragma unroll
    for (int s = 0; s < S_SUP; s++) p += z[s * ZD];
    p *= (1.0f / S_SUP);
    const int k16 = d >> 4;
    const int kk  = d & 15;
    const int pos = ((kk >> 1) & 3) * 4 + ((kk >> 3) & 1) * 2 + (kk & 1);
    const __half hi = __float2half_rn(p);
    const int off = k16 * 4096 + c * 16 + pos;
    g_Ph[off] = hi;
    g_Pl[off] = __float2half_rn(p - __half2float(hi));
    float sq = p * p;
#pragma unroll
    for (int o = 16; o; o >>= 1) sq += __shfl_xor_sync(0xffffffffu, sq, o);
    __shared__ float w[4];
    if ((d & 31) == 0) w[d >> 5] = sq;
    __syncthreads();
    if (d == 0) g_proto2[c] = w[0] + w[1] + w[2] + w[3];
}

// =====================================================================
// K3 (fused d2 + loo): one CTA per 2 classes. GEMM M=128 x N=256 x K=128,
// fp16 double-double 3-pass, warp tile 32x64 (16 warps: 4m x 4n).
// d2 -> SMEM (stride 264), then in-CTA loo-norm + cos identity + argmin.
// cos: sum_{q<k} a_q.a_k = ( ||sum_q a_q||^2 - sum_q ||a_q||^2 ) / 2
// =====================================================================
__global__ __launch_bounds__(512) void k_dloo(){
    extern __shared__ __half sh[];       // buffers; d2s aliases as float*
    __shared__ float s_part[16][256];
    __shared__ float s_red[16];
    __shared__ float s_scal[4];          // [sumA2_c0, cnt_c0, sumA2_c1, cnt_c1]

    const int tid  = threadIdx.x;
    const int lane = tid & 31;
    const int wid  = tid >> 5;           // 0..15
    const int g    = lane >> 2;
    const int tg   = lane & 3;
    const int m0   = (wid & 3) * 32;
    const int n0   = (wid >> 2) * 64;
    const int qb   = blockIdx.x;         // class pair
    const float* X = g_z + (size_t)(CS + qb * 128) * ZD;
    const int sm_m = tid >> 2;
    const int st   = tid & 3;
    const int sts_off = sm_m * 16 + st * 4;

    if (tid < 4) s_scal[tid] = 0.0f;

    float4 acc[2][8];
#pragma unroll
    for (int i = 0; i < 2; i++)
#pragma unroll
        for (int j = 0; j < 8; j++) acc[i][j] = make_float4(0.f, 0.f, 0.f, 0.f);

    float2 rA0, rA1;
    // prologue: stage 0
    {
        __half* buf = sh;
        cp16(smem_u32(&buf[D_BH]) + tid * 16, g_Ph + tid * 8);
        cp16(smem_u32(&buf[D_BL]) + tid * 16, g_Pl + tid * 8);
        CP_COMMIT();
        const float* xp = X + (size_t)sm_m * ZD + 2 * st;
        rA0 = *(const float2*)xp;
        rA1 = *(const float2*)(xp + 8);
        uint32_t h01, l01, h89, l89;
        hsplit2(rA0, h01, l01);
        hsplit2(rA1, h89, l89);
        *(uint2*)&buf[sts_off]        = make_uint2(h01, h89);
        *(uint2*)&buf[D_AL + sts_off] = make_uint2(l01, l89);
        CP_WAIT0();
    }
    __syncthreads();

    for (int s = 0; s < DLSTG; s++){
        const int b = s & 1;
        const __half* buf = sh + b * D_BUF;
        __half* nbuf = sh + (b ^ 1) * D_BUF;
        if (s + 1 < DLSTG){
            cp16(smem_u32(&nbuf[D_BH]) + tid * 16, g_Ph + (s + 1) * 4096 + tid * 8);
            cp16(smem_u32(&nbuf[D_BL]) + tid * 16, g_Pl + (s + 1) * 4096 + tid * 8);
            CP_COMMIT();
            const float* xp = X + (size_t)sm_m * ZD + (s + 1) * 16 + 2 * st;
            rA0 = *(const float2*)xp;
            rA1 = *(const float2*)(xp + 8);
        }
        uint2 AH[2][2], AL[2][2];
#pragma unroll
        for (int mt = 0; mt < 2; mt++){
            const int r0 = (m0 + mt * 16 + g) * 16 + tg * 4;
            AH[mt][0] = *(const uint2*)&buf[r0];
            AH[mt][1] = *(const uint2*)&buf[r0 + 128];
            AL[mt][0] = *(const uint2*)&buf[D_AL + r0];
            AL[mt][1] = *(const uint2*)&buf[D_AL + r0 + 128];
        }
#pragma unroll
        for (int j = 0; j < 8; j++){
            const int nb = (n0 + j * 8 + g) * 16 + tg * 4;
            const uint2 bh = *(const uint2*)&buf[D_BH + nb];
            const uint2 bl = *(const uint2*)&buf[D_BL + nb];
#pragma unroll
            for (int mt = 0; mt < 2; mt++){
                mma16(acc[mt][j], AH[mt][0].x, AH[mt][1].x, AH[mt][0].y, AH[mt][1].y, bh.x, bh.y);
                mma16(acc[mt][j], AL[mt][0].x, AL[mt][1].x, AL[mt][0].y, AL[mt][1].y, bh.x, bh.y);
                mma16(acc[mt][j], AH[mt][0].x, AH[mt][1].x, AH[mt][0].y, AH[mt][1].y, bl.x, bl.y);
            }
        }
        if (s + 1 < DLSTG){
            uint32_t h01, l01, h89, l89;
            hsplit2(rA0, h01, l01);
            hsplit2(rA1, h89, l89);
            *(uint2*)&nbuf[sts_off]        = make_uint2(h01, h89);
            *(uint2*)&nbuf[D_AL + sts_off] = make_uint2(l01, l89);
            CP_WAIT0();
            __syncthreads();
        }
    }

    // ---- d2 into SMEM (reuses stage buffers; stride 264 floats) ----
    __syncthreads();                     // all warps done reading buffers
    float* d2s = (float*)sh;             // 128 x 264 floats
#pragma unroll
    for (int mt = 0; mt < 2; mt++){
        const int r = m0 + mt * 16 + g;
        const float qn0 = g_row2[CS + qb * 128 + r];
        const float qn1 = g_row2[CS + qb * 128 + r + 8];
#pragma unroll
        for (int j = 0; j < 8; j++){
            const int col = n0 + j * 8 + 2 * tg;
            const float pn0 = g_proto2[col];
            const float pn1 = g_proto2[col + 1];
            const float4 a = acc[mt][j];
            *(float2*)&d2s[r * 264 + col] =
                make_float2(qn0 + pn0 - 2.0f * a.x, qn0 + pn1 - 2.0f * a.y);
            *(float2*)&d2s[(r + 8) * 264 + col] =
                make_float2(qn1 + pn0 - 2.0f * a.z, qn1 + pn1 - 2.0f * a.w);
        }
    }
    __syncthreads();

    // ---- loo: warp w -> rows w*8..w*8+7; class = 2qb + (w>>3) ----
    const int cls = 2 * qb + (wid >> 3);
    const float* D = d2s + (size_t)(wid * 8) * 264 + lane * 8;
    float d2v[8][8];
#pragma unroll
    for (int r = 0; r < 8; r++){
        const float4 v0 = *(const float4*)(D + r * 264);
        const float4 v1 = *(const float4*)(D + r * 264 + 4);
        d2v[r][0] = v0.x; d2v[r][1] = v0.y; d2v[r][2] = v0.z; d2v[r][3] = v0.w;
        d2v[r][4] = v1.x; d2v[r][5] = v1.y; d2v[r][6] = v1.z; d2v[r][7] = v1.w;
    }

    float sacc[8];
#pragma unroll
    for (int j = 0; j < 8; j++) sacc[j] = 0.0f;
    float sumA2 = 0.0f;
    float cnt   = 0.0f;

#pragma unroll
    for (int r = 0; r < 8; r++){
        float ss = 0.0f;
        float mv = 3.4e38f;
        int   mi = 1 << 30;
#pragma unroll
        for (int j = 0; j < 8; j++){
            const int   p = lane * 8 + j;
            const float v = d2v[r][j];
            if (v < mv){ mv = v; mi = p; }        // ascending -> first min
            if (p != cls) ss = fmaf(v, v, ss);
        }
#pragma unroll
        for (int off = 16; off; off >>= 1){
            ss += __shfl_xor_sync(0xffffffffu, ss, off);
            const float ov = __shfl_xor_sync(0xffffffffu, mv, off);
            const int   oi = __shfl_xor_sync(0xffffffffu, mi, off);
            if (ov < mv || (ov == mv && oi < mi)){ mv = ov; mi = oi; }
        }
        const float inv = 1.0f / fmaxf(sqrtf(ss), EPSF);
#pragma unroll
        for (int j = 0; j < 8; j++){
            const int p = lane * 8 + j;
            if (p != cls) sacc[j] = fmaf(d2v[r][j], inv, sacc[j]);
        }
        if (lane == 0){
            sumA2 += ss * inv * inv;
            if (mi == cls) cnt += 1.0f;
        }
    }

#pragma unroll
    for (int j = 0; j < 8; j++) s_part[wid][lane * 8 + j] = sacc[j];
    if (lane == 0){
        atomicAdd(&s_scal[(wid >> 3) * 2],     sumA2);
        atomicAdd(&s_scal[(wid >> 3) * 2 + 1], cnt);
    }
    __syncthreads();

    // ||sum_q a_q||^2 per class: threads 0-255 -> class0, 256-511 -> class1
    {
        const int half = tid >> 8;
        const int cc   = tid & 255;
        float col = 0.0f;
#pragma unroll
        for (int w2 = 0; w2 < 8; w2++) col += s_part[half * 8 + w2][cc];
        float sq = col * col;
#pragma unroll
        for (int off = 16; off; off >>= 1) sq += __shfl_xor_sync(0xffffffffu, sq, off);
        if (lane == 0) s_red[wid] = sq;
    }
    __syncthreads();
    if (tid == 0){
        float S20 = 0.0f, S21 = 0.0f;
#pragma unroll
        for (int i = 0; i < 8; i++){ S20 += s_red[i]; S21 += s_red[8 + i]; }
        atomicAdd(&g_cos_sum, 0.5f * ((S20 - s_scal[0]) + (S21 - s_scal[2])));
        atomicAdd(&g_acc_cnt, s_scal[1] + s_scal[3]);
    }
}

// ---------------- K4: finalize -------------------------------------------
__global__ void k_final(float* __restrict__ out){
    if (threadIdx.x == 0){
        out[0] = g_cos_sum / (float)NPAIRS;
        out[1] = g_acc_cnt / (float)CQ;
    }
}

// ---------------- launch ---------------------------------------------------
extern "C" void kernel_launch(void* const* d_in, const int* in_sizes, int n_in,
                              void* d_out, int out_size){
    const float* xs = (const float*)d_in[0];
    const float* xq = (const float*)d_in[1];
    const float* W  = (const float*)d_in[2];
    float* out = (float*)d_out;
    (void)in_sizes; (void)n_in; (void)out_size;

    const int smem_gemm = 2 * G_BUF * (int)sizeof(__half);      // 32 KB
    const int smem_dloo = 128 * 264 * (int)sizeof(float);       // 135 KB (>= 2*D_BUF*2B)
    cudaFuncSetAttribute(k_gemm, cudaFuncAttributeMaxDynamicSharedMemorySize, smem_gemm);
    cudaFuncSetAttribute(k_dloo, cudaFuncAttributeMaxDynamicSharedMemorySize, smem_dloo);

    k_wsplit<<<64, 256>>>(W);
    k_gemm<<<M_TOT / 128, 1024, smem_gemm>>>(xs, xq);
    k_proto<<<C_CLS, 128>>>();
    k_dloo<<<128, 512, smem_dloo>>>();
    k_final<<<1, 1>>>(out);
}

// round 15
// speedup vs baseline: 1.2765x; 1.1355x over previous
#include <cuda_runtime.h>
#include <cuda_fp16.h>
#include <cstdint>

// Problem constants (fixed by reference setup_inputs)
#define C_CLS 256
#define S_SUP 5
#define Q_QRY 64
#define DIN   1024
#define ZD    128
#define CS    (C_CLS*S_SUP)              // 1280
#define CQ    (C_CLS*Q_QRY)              // 16384
#define M_TOT (CS+CQ)                    // 17664
#define NPAIRS (C_CLS*(Q_QRY*(Q_QRY-1)/2)) // 516096
#define EPSF  1e-8f
#define NSTG  64                          // k_gemm: K stages of 16
#define DLSTG 8                           // k_dloo: K stages of 16
#define RPAD  24                          // padded row length (halves) = 48B

// k_gemm smem halves/buffer: Ah 3072 | Al 3072 | Bh 3072 | Bl 3072
#define G_BUF 12288                       // 24 KB / buffer
// k_dloo smem halves/buffer: Ah 3072 | Al 3072 | Bh 6144 | Bl 6144
#define D_BUF 18432                       // 36 KB / buffer

// ---------------- device scratch (no allocations allowed) ----------------
__device__ __align__(16) float g_z[(size_t)M_TOT * ZD];        // ~9 MB
__device__ __align__(16) float g_proto2[C_CLS];                // ||proto_c||^2
__device__ __align__(16) float g_row2[M_TOT];                  // ||z_row||^2
// 32*W fp16 hi/lo images, natural padded: [k16(64)][n(128)][RPAD]
__device__ __align__(16) __half g_Wh[64 * 128 * RPAD];         // 384 KB
__device__ __align__(16) __half g_Wl[64 * 128 * RPAD];         // 384 KB
// protoT fp16 hi/lo images: [k16(8)][n(256)][RPAD]
__device__ __align__(16) __half g_Ph[8 * 256 * RPAD];          // 96 KB
__device__ __align__(16) __half g_Pl[8 * 256 * RPAD];          // 96 KB
__device__ float g_cos_sum;
__device__ float g_acc_cnt;

// ---------------- helpers ----------------
__device__ __forceinline__ uint32_t smem_u32(const void* p){
    uint32_t a; asm("{ .reg .u64 t; cvta.to.shared.u64 t, %1; cvt.u32.u64 %0, t; }"
                    : "=r"(a) : "l"(p));
    return a;
}
__device__ __forceinline__ void cp16(uint32_t saddr, const void* g){
    asm volatile("cp.async.cg.shared.global [%0], [%1], 16;" :: "r"(saddr), "l"(g));
}
#define CP_COMMIT() asm volatile("cp.async.commit_group;" ::: "memory")
#define CP_WAIT0()  asm volatile("cp.async.wait_group 0;"  ::: "memory")

// ldmatrix x4 (4 x m8n8 b16 matrices)
__device__ __forceinline__ void ldm4(uint32_t* r, uint32_t addr){
    asm volatile("ldmatrix.sync.aligned.m8n8.x4.shared.b16 {%0,%1,%2,%3}, [%4];"
        : "=r"(r[0]), "=r"(r[1]), "=r"(r[2]), "=r"(r[3]) : "r"(addr));
}
// D += A(16x16,row) * B(16x8,col)  fp16 inputs, fp32 accumulate
__device__ __forceinline__ void mma16(float4 &d, uint32_t a0, uint32_t a1,
                                      uint32_t a2, uint32_t a3,
                                      uint32_t b0, uint32_t b1){
    asm volatile("mma.sync.aligned.m16n8k16.row.col.f32.f16.f16.f32 "
        "{%0,%1,%2,%3}, {%4,%5,%6,%7}, {%8,%9}, {%0,%1,%2,%3};"
        : "+f"(d.x), "+f"(d.y), "+f"(d.z), "+f"(d.w)
        : "r"(a0), "r"(a1), "r"(a2), "r"(a3), "r"(b0), "r"(b1));
}
// split float4 (4 consecutive k) -> packed hi uint2 + lo uint2
__device__ __forceinline__ void hsplit4(float4 v, uint2 &hi, uint2 &lo){
    __half2 ha = __float22half2_rn(make_float2(v.x, v.y));
    __half2 hb = __float22half2_rn(make_float2(v.z, v.w));
    float2 fa = __half22float2(ha), fb = __half22float2(hb);
    __half2 la = __float22half2_rn(make_float2(v.x - fa.x, v.y - fa.y));
    __half2 lb = __float22half2_rn(make_float2(v.z - fb.x, v.w - fb.y));
    hi = make_uint2(*(uint32_t*)&ha, *(uint32_t*)&hb);
    lo = make_uint2(*(uint32_t*)&la, *(uint32_t*)&lb);
}

// =====================================================================
// KW: split 32*W into fp16 hi/lo NATURAL padded images [s][n][RPAD].
// Thread t: n = t>>1, h = t&1 covers k-halves 8h..8h+7.
// =====================================================================
__global__ __launch_bounds__(256) void k_wsplit(const float* __restrict__ W){
    const int s = blockIdx.x;            // 0..63
    const int n = threadIdx.x >> 1;
    const int h = threadIdx.x & 1;
    const int kb = s * 16 + 8 * h;
    float4 v0, v1;
    v0.x = 32.f * W[(size_t)(kb + 0) * ZD + n];
    v0.y = 32.f * W[(size_t)(kb + 1) * ZD + n];
    v0.z = 32.f * W[(size_t)(kb + 2) * ZD + n];
    v0.w = 32.f * W[(size_t)(kb + 3) * ZD + n];
    v1.x = 32.f * W[(size_t)(kb + 4) * ZD + n];
    v1.y = 32.f * W[(size_t)(kb + 5) * ZD + n];
    v1.z = 32.f * W[(size_t)(kb + 6) * ZD + n];
    v1.w = 32.f * W[(size_t)(kb + 7) * ZD + n];
    uint2 h0, l0, h1, l1;
    hsplit4(v0, h0, l0);
    hsplit4(v1, h1, l1);
    const int off = s * (128 * RPAD) + n * RPAD + 8 * h;   // halves, 16B aligned
    *(uint4*)&g_Wh[off] = make_uint4(h0.x, h0.y, h1.x, h1.y);
    *(uint4*)&g_Wl[off] = make_uint4(l0.x, l0.y, l1.x, l1.y);
}

// =====================================================================
// K1: z = [xs; xq] @ W, fp16 double-double (3-pass m16n8k16), fragments
// via ldmatrix.x4 on padded (48B-row, conflict-free) natural layout.
// 512 threads = 16 warps (4m x 4n), warp tile 32x32, 64 stages,
// double-buffered 2x24KB. B via cp.async; A split at staging.
// Epilogue: z = acc/32 + fused ||row||^2.
// =====================================================================
__global__ __launch_bounds__(512) void k_gemm(const float* __restrict__ xs,
                                              const float* __restrict__ xq){
    extern __shared__ __half sh[];       // 2 x G_BUF halves (48 KB)
    __shared__ float s_r2[128];

    const int tid  = threadIdx.x;
    const int lane = tid & 31;
    const int wid  = tid >> 5;
    const int g    = lane >> 2;
    const int tg   = lane & 3;
    const int m0   = (wid & 3) * 32;
    const int n0   = (wid >> 2) * 32;
    const int bm   = blockIdx.x;
    const float* X = (bm < 10) ? (xs + (size_t)bm * (128 * DIN))
                               : (xq + (size_t)(bm - 10) * (128 * DIN));
    const int sm_m = tid >> 2;           // staging row 0..127
    const int sq   = tid & 3;            // k quad
    const uint32_t sbase = smem_u32(sh);

    // fragment addresses (bytes rel. to buffer): A mats T00,T10,T01,T11
    const int arow  = lane & 15;
    const int akoff = ((lane >> 4) & 1) * 8;
    uint32_t aAddr[2];
#pragma unroll
    for (int mt = 0; mt < 2; mt++)
        aAddr[mt] = sbase + ((m0 + mt * 16 + arow) * RPAD + akoff) * 2;
    // B mats (j0,k0),(j0,k8),(j1,k0),(j1,k8)
    const int brow  = (lane & 7) + ((lane >> 4) & 1) * 8;
    const int bkoff = ((lane >> 3) & 1) * 8;
    uint32_t bAddr[2];
#pragma unroll
    for (int jp = 0; jp < 2; jp++)
        bAddr[jp] = sbase + (6144 + (n0 + jp * 16 + brow) * RPAD + bkoff) * 2;

    float4 acc[2][4];
#pragma unroll
    for (int i = 0; i < 2; i++)
#pragma unroll
        for (int j = 0; j < 4; j++) acc[i][j] = make_float4(0.f, 0.f, 0.f, 0.f);

    float4 rA;
    // prologue: stage 0
    {
        // B: hi 3072 halves = 384 cp16 (tids 0-383); lo (tids 128-511)
        if (tid < 384)  cp16(sbase + 12288 + tid * 16, g_Wh + tid * 8);
        if (tid >= 128) cp16(sbase + 18432 + (tid - 128) * 16, g_Wl + (tid - 128) * 8);
        CP_COMMIT();
        rA = *(const float4*)(X + (size_t)sm_m * DIN + sq * 4);
        uint2 hi, lo;
        hsplit4(rA, hi, lo);
        *(uint2*)&sh[sm_m * RPAD + sq * 4]        = hi;
        *(uint2*)&sh[3072 + sm_m * RPAD + sq * 4] = lo;
        CP_WAIT0();
    }
    __syncthreads();

    for (int s = 0; s < NSTG; s++){
        const int b = s & 1;
        const uint32_t boff = b * (G_BUF * 2);
        __half* nbuf = sh + (b ^ 1) * G_BUF;
        if (s + 1 < NSTG){
            const uint32_t nb = sbase + (b ^ 1) * (G_BUF * 2);
            const __half* srcH = g_Wh + (s + 1) * (128 * RPAD);
            const __half* srcL = g_Wl + (s + 1) * (128 * RPAD);
            if (tid < 384)  cp16(nb + 12288 + tid * 16, srcH + tid * 8);
            if (tid >= 128) cp16(nb + 18432 + (tid - 128) * 16, srcL + (tid - 128) * 8);
            CP_COMMIT();
            rA = *(const float4*)(X + (size_t)sm_m * DIN + (s + 1) * 16 + sq * 4);
        }
        // A fragments: 4 ldmatrix.x4 (mt x hi/lo)
        uint32_t ah[2][4], al[2][4];
#pragma unroll
        for (int mt = 0; mt < 2; mt++){
            ldm4(ah[mt], aAddr[mt] + boff);
            ldm4(al[mt], aAddr[mt] + boff + 6144);
        }
#pragma unroll
        for (int jp = 0; jp < 2; jp++){
            uint32_t bh[4], bl[4];
            ldm4(bh, bAddr[jp] + boff);
            ldm4(bl, bAddr[jp] + boff + 6144);
#pragma unroll
            for (int mt = 0; mt < 2; mt++){
                mma16(acc[mt][2*jp],   ah[mt][0], ah[mt][1], ah[mt][2], ah[mt][3], bh[0], bh[1]);
                mma16(acc[mt][2*jp+1], ah[mt][0], ah[mt][1], ah[mt][2], ah[mt][3], bh[2], bh[3]);
                mma16(acc[mt][2*jp],   al[mt][0], al[mt][1], al[mt][2], al[mt][3], bh[0], bh[1]);
                mma16(acc[mt][2*jp+1], al[mt][0], al[mt][1], al[mt][2], al[mt][3], bh[2], bh[3]);
                mma16(acc[mt][2*jp],   ah[mt][0], ah[mt][1], ah[mt][2], ah[mt][3], bl[0], bl[1]);
                mma16(acc[mt][2*jp+1], ah[mt][0], ah[mt][1], ah[mt][2], ah[mt][3], bl[2], bl[3]);
            }
        }
        if (s + 1 < NSTG){
            uint2 hi, lo;
            hsplit4(rA, hi, lo);
            *(uint2*)&nbuf[sm_m * RPAD + sq * 4]        = hi;
            *(uint2*)&nbuf[3072 + sm_m * RPAD + sq * 4] = lo;
            CP_WAIT0();
            __syncthreads();
        }
    }

    // ---- epilogue: z = acc/32, store + fused row norms ----
    if (tid < 128) s_r2[tid] = 0.0f;
    __syncthreads();
    const size_t rb = (size_t)bm * 128;
    const float inv32 = 1.0f / 32.0f;
#pragma unroll
    for (int mt = 0; mt < 2; mt++){
        const int r0 = m0 + mt * 16 + g;
        float s0 = 0.0f, s1 = 0.0f;
#pragma unroll
        for (int j = 0; j < 4; j++){
            float4 a = acc[mt][j];
            a.x *= inv32; a.y *= inv32; a.z *= inv32; a.w *= inv32;
            const int col = n0 + j * 8 + 2 * tg;
            *(float2*)(g_z + (rb + r0) * ZD + col)     = make_float2(a.x, a.y);
            *(float2*)(g_z + (rb + r0 + 8) * ZD + col) = make_float2(a.z, a.w);
            s0 = fmaf(a.x, a.x, s0); s0 = fmaf(a.y, a.y, s0);
            s1 = fmaf(a.z, a.z, s1); s1 = fmaf(a.w, a.w, s1);
        }
        s0 += __shfl_xor_sync(0xffffffffu, s0, 1);
        s0 += __shfl_xor_sync(0xffffffffu, s0, 2);
        s1 += __shfl_xor_sync(0xffffffffu, s1, 1);
        s1 += __shfl_xor_sync(0xffffffffu, s1, 2);
        if (tg == 0){
            atomicAdd(&s_r2[r0],     s0);
            atomicAdd(&s_r2[r0 + 8], s1);
        }
    }
    __syncthreads();
    if (tid < 128) g_row2[rb + tid] = s_r2[tid];
}

// ---------------- K2: prototypes + ||proto||^2 + padded hi/lo images ----
__global__ __launch_bounds__(128) void k_proto(){
    const int c = blockIdx.x;
    const int d = threadIdx.x;  // 0..127 (= k index)
    if (c == 0 && d == 0){ g_cos_sum = 0.0f; g_acc_cnt = 0.0f; }
    const float* z = g_z + (size_t)c * S_SUP * ZD + d;
    float p = 0.0f;
#pragma unroll
    for (int s = 0; s < S_SUP; s++) p += z[s * ZD];
    p *= (1.0f / S_SUP);
    const __half hi = __float2half_rn(p);
    const int off = (d >> 4) * (256 * RPAD) + c * RPAD + (d & 15);
    g_Ph[off] = hi;
    g_Pl[off] = __float2half_rn(p - __half2float(hi));
    float sq = p * p;
#pragma unroll
    for (int o = 16; o; o >>= 1) sq += __shfl_xor_sync(0xffffffffu, sq, o);
    __shared__ float w[4];
    if ((d & 31) == 0) w[d >> 5] = sq;
    __syncthreads();
    if (d == 0) g_proto2[c] = w[0] + w[1] + w[2] + w[3];
}

// =====================================================================
// K3 (fused d2 + loo): one CTA per 2 classes. GEMM M=128 x N=256 x K=128,
// fp16 double-double 3-pass via ldmatrix.x4, warp tile 32x64
// (16 warps: 4m x 4n). d2 -> SMEM (stride 264) then loo + cos + argmin.
// cos: sum_{q<k} a_q.a_k = ( ||sum_q a_q||^2 - sum_q ||a_q||^2 ) / 2
// =====================================================================
__global__ __launch_bounds__(512) void k_dloo(){
    extern __shared__ __half sh[];       // buffers; d2s aliases as float*
    __shared__ float s_part[16][256];
    __shared__ float s_red[16];
    __shared__ float s_scal[4];          // [sumA2_c0, cnt_c0, sumA2_c1, cnt_c1]

    const int tid  = threadIdx.x;
    const int lane = tid & 31;
    const int wid  = tid >> 5;           // 0..15
    const int g    = lane >> 2;
    const int tg   = lane & 3;
    const int m0   = (wid & 3) * 32;
    const int n0   = (wid >> 2) * 64;
    const int qb   = blockIdx.x;         // class pair
    const float* X = g_z + (size_t)(CS + qb * 128) * ZD;
    const int sm_m = tid >> 2;
    const int sq   = tid & 3;
    const uint32_t sbase = smem_u32(sh);

    if (tid < 4) s_scal[tid] = 0.0f;

    const int arow  = lane & 15;
    const int akoff = ((lane >> 4) & 1) * 8;
    uint32_t aAddr[2];
#pragma unroll
    for (int mt = 0; mt < 2; mt++)
        aAddr[mt] = sbase + ((m0 + mt * 16 + arow) * RPAD + akoff) * 2;
    const int brow  = (lane & 7) + ((lane >> 4) & 1) * 8;
    const int bkoff = ((lane >> 3) & 1) * 8;
    uint32_t bAddr[4];
#pragma unroll
    for (int jp = 0; jp < 4; jp++)
        bAddr[jp] = sbase + (6144 + (n0 + jp * 16 + brow) * RPAD + bkoff) * 2;

    float4 acc[2][8];
#pragma unroll
    for (int i = 0; i < 2; i++)
#pragma unroll
        for (int j = 0; j < 8; j++) acc[i][j] = make_float4(0.f, 0.f, 0.f, 0.f);

    float4 rA;
    // prologue: stage 0. B: 6144 halves = 768 cp16 per image.
    {
#pragma unroll
        for (int e = 0; e < 2; e++){
            const int idx = tid + e * 512;
            if (idx < 768){
                cp16(sbase + 12288 + idx * 16, g_Ph + idx * 8);
                cp16(sbase + 24576 + idx * 16, g_Pl + idx * 8);
            }
        }
        CP_COMMIT();
        rA = *(const float4*)(X + (size_t)sm_m * ZD + sq * 4);
        uint2 hi, lo;
        hsplit4(rA, hi, lo);
        *(uint2*)&sh[sm_m * RPAD + sq * 4]        = hi;
        *(uint2*)&sh[3072 + sm_m * RPAD + sq * 4] = lo;
        CP_WAIT0();
    }
    __syncthreads();

    for (int s = 0; s < DLSTG; s++){
        const int b = s & 1;
        const uint32_t boff = b * (D_BUF * 2);
        __half* nbuf = sh + (b ^ 1) * D_BUF;
        if (s + 1 < DLSTG){
            const uint32_t nb = sbase + (b ^ 1) * (D_BUF * 2);
            const __half* srcH = g_Ph + (s + 1) * (256 * RPAD);
            const __half* srcL = g_Pl + (s + 1) * (256 * RPAD);
#pragma unroll
            for (int e = 0; e < 2; e++){
                const int idx = tid + e * 512;
                if (idx < 768){
                    cp16(nb + 12288 + idx * 16, srcH + idx * 8);
                    cp16(nb + 24576 + idx * 16, srcL + idx * 8);
                }
            }
            CP_COMMIT();
            rA = *(const float4*)(X + (size_t)sm_m * ZD + (s + 1) * 16 + sq * 4);
        }
        uint32_t ah[2][4], al[2][4];
#pragma unroll
        for (int mt = 0; mt < 2; mt++){
            ldm4(ah[mt], aAddr[mt] + boff);
            ldm4(al[mt], aAddr[mt] + boff + 6144);
        }
#pragma unroll
        for (int jp = 0; jp < 4; jp++){
            uint32_t bh[4], bl[4];
            ldm4(bh, bAddr[jp] + boff);
            ldm4(bl, bAddr[jp] + boff + 12288);
#pragma unroll
            for (int mt = 0; mt < 2; mt++){
                mma16(acc[mt][2*jp],   ah[mt][0], ah[mt][1], ah[mt][2], ah[mt][3], bh[0], bh[1]);
                mma16(acc[mt][2*jp+1], ah[mt][0], ah[mt][1], ah[mt][2], ah[mt][3], bh[2], bh[3]);
                mma16(acc[mt][2*jp],   al[mt][0], al[mt][1], al[mt][2], al[mt][3], bh[0], bh[1]);
                mma16(acc[mt][2*jp+1], al[mt][0], al[mt][1], al[mt][2], al[mt][3], bh[2], bh[3]);
                mma16(acc[mt][2*jp],   ah[mt][0], ah[mt][1], ah[mt][2], ah[mt][3], bl[0], bl[1]);
                mma16(acc[mt][2*jp+1], ah[mt][0], ah[mt][1], ah[mt][2], ah[mt][3], bl[2], bl[3]);
            }
        }
        if (s + 1 < DLSTG){
            uint2 hi, lo;
            hsplit4(rA, hi, lo);
            *(uint2*)&nbuf[sm_m * RPAD + sq * 4]        = hi;
            *(uint2*)&nbuf[3072 + sm_m * RPAD + sq * 4] = lo;
            CP_WAIT0();
            __syncthreads();
        }
    }

    // ---- d2 into SMEM (reuses stage buffers; stride 264 floats) ----
    __syncthreads();                     // all warps done reading buffers
    float* d2s = (float*)sh;             // 128 x 264 floats
#pragma unroll
    for (int mt = 0; mt < 2; mt++){
        const int r = m0 + mt * 16 + g;
        const float qn0 = g_row2[CS + qb * 128 + r];
        const float qn1 = g_row2[CS + qb * 128 + r + 8];
#pragma unroll
        for (int j = 0; j < 8; j++){
            const int col = n0 + j * 8 + 2 * tg;
            const float pn0 = g_proto2[col];
            const float pn1 = g_proto2[col + 1];
            const float4 a = acc[mt][j];
            *(float2*)&d2s[r * 264 + col] =
                make_float2(qn0 + pn0 - 2.0f * a.x, qn0 + pn1 - 2.0f * a.y);
            *(float2*)&d2s[(r + 8) * 264 + col] =
                make_float2(qn1 + pn0 - 2.0f * a.z, qn1 + pn1 - 2.0f * a.w);
        }
    }
    __syncthreads();

    // ---- loo: warp w -> rows w*8..w*8+7; class = 2qb + (w>>3) ----
    const int cls = 2 * qb + (wid >> 3);
    const float* D = d2s + (size_t)(wid * 8) * 264 + lane * 8;
    float d2v[8][8];
#pragma unroll
    for (int r = 0; r < 8; r++){
        const float4 v0 = *(const float4*)(D + r * 264);
        const float4 v1 = *(const float4*)(D + r * 264 + 4);
        d2v[r][0] = v0.x; d2v[r][1] = v0.y; d2v[r][2] = v0.z; d2v[r][3] = v0.w;
        d2v[r][4] = v1.x; d2v[r][5] = v1.y; d2v[r][6] = v1.z; d2v[r][7] = v1.w;
    }

    float sacc[8];
#pragma unroll
    for (int j = 0; j < 8; j++) sacc[j] = 0.0f;
    float sumA2 = 0.0f;
    float cnt   = 0.0f;

#pragma unroll
    for (int r = 0; r < 8; r++){
        float ss = 0.0f;
        float mv = 3.4e38f;
        int   mi = 1 << 30;
#pragma unroll
        for (int j = 0; j < 8; j++){
            const int   p = lane * 8 + j;
            const float v = d2v[r][j];
            if (v < mv){ mv = v; mi = p; }        // ascending -> first min
            if (p != cls) ss = fmaf(v, v, ss);
        }
#pragma unroll
        for (int off = 16; off; off >>= 1){
            ss += __shfl_xor_sync(0xffffffffu, ss, off);
            const float ov = __shfl_xor_sync(0xffffffffu, mv, off);
            const int   oi = __shfl_xor_sync(0xffffffffu, mi, off);
            if (ov < mv || (ov == mv && oi < mi)){ mv = ov; mi = oi; }
        }
        const float inv = 1.0f / fmaxf(sqrtf(ss), EPSF);
#pragma unroll
        for (int j = 0; j < 8; j++){
            const int p = lane * 8 + j;
            if (p != cls) sacc[j] = fmaf(d2v[r][j], inv, sacc[j]);
        }
        if (lane == 0){
            sumA2 += ss * inv * inv;
            if (mi == cls) cnt += 1.0f;
        }
    }

#pragma unroll
    for (int j = 0; j < 8; j++) s_part[wid][lane * 8 + j] = sacc[j];
    if (lane == 0){
        atomicAdd(&s_scal[(wid >> 3) * 2],     sumA2);
        atomicAdd(&s_scal[(wid >> 3) * 2 + 1], cnt);
    }
    __syncthreads();

    // ||sum_q a_q||^2 per class: threads 0-255 -> class0, 256-511 -> class1
    {
        const int half = tid >> 8;
        const int cc   = tid & 255;
        float col = 0.0f;
#pragma unroll
        for (int w2 = 0; w2 < 8; w2++) col += s_part[half * 8 + w2][cc];
        float sq = col * col;
#pragma unroll
        for (int off = 16; off; off >>= 1) sq += __shfl_xor_sync(0xffffffffu, sq, off);
        if (lane == 0) s_red[wid] = sq;
    }
    __syncthreads();
    if (tid == 0){
        float S20 = 0.0f, S21 = 0.0f;
#pragma unroll
        for (int i = 0; i < 8; i++){ S20 += s_red[i]; S21 += s_red[8 + i]; }
        atomicAdd(&g_cos_sum, 0.5f * ((S20 - s_scal[0]) + (S21 - s_scal[2])));
        atomicAdd(&g_acc_cnt, s_scal[1] + s_scal[3]);
    }
}

// ---------------- K4: finalize -------------------------------------------
__global__ void k_final(float* __restrict__ out){
    if (threadIdx.x == 0){
        out[0] = g_cos_sum / (float)NPAIRS;
        out[1] = g_acc_cnt / (float)CQ;
    }
}

// ---------------- launch ---------------------------------------------------
extern "C" void kernel_launch(void* const* d_in, const int* in_sizes, int n_in,
                              void* d_out, int out_size){
    const float* xs = (const float*)d_in[0];
    const float* xq = (const float*)d_in[1];
    const float* W  = (const float*)d_in[2];
    float* out = (float*)d_out;
    (void)in_sizes; (void)n_in; (void)out_size;

    const int smem_gemm = 2 * G_BUF * (int)sizeof(__half);      // 48 KB
    const int smem_dloo = 128 * 264 * (int)sizeof(float);       // 135 KB (>= 2*D_BUF*2B)
    cudaFuncSetAttribute(k_gemm, cudaFuncAttributeMaxDynamicSharedMemorySize, smem_gemm);
    cudaFuncSetAttribute(k_dloo, cudaFuncAttributeMaxDynamicSharedMemorySize, smem_dloo);

    k_wsplit<<<64, 256>>>(W);
    k_gemm<<<M_TOT / 128, 512, smem_gemm>>>(xs, xq);
    k_proto<<<C_CLS, 128>>>();
    k_dloo<<<128, 512, smem_dloo>>>();
    k_final<<<1, 1>>>(out);
}